// round 3
// baseline (speedup 1.0000x reference)
#include <cuda_runtime.h>

// NeuralODE RK4, round 3: col-packed f32x2 accumulators, duplicated activations
// in SMEM (broadcast LDS feeds both lanes), weights consumed straight from
// LDG.128 (zero pack MOVs), double-buffered weight prefetch to hide L2 latency.
// 256 CTAs x 8 rows, 2 CTAs/SM.

#define B_DIM   2048
#define F_DIM   256
#define H_DIM   1024
#define NSTEPS  100
#define ROWS    8
#define NTHREADS 256
#define NCTA    (B_DIM / ROWS)   // 256

typedef unsigned long long ull;

__device__ __forceinline__ void fma2(ull &d, ull a, ull b) {
    asm("fma.rn.f32x2 %0, %1, %2, %0;" : "+l"(d) : "l"(a), "l"(b));
}
__device__ __forceinline__ ull pack2(float x, float y) {
    ull r; asm("mov.b64 %0, {%1, %2};" : "=l"(r) : "f"(x), "f"(y)); return r;
}
__device__ __forceinline__ float2 unpack2(ull v) {
    float2 f; asm("mov.b64 {%0, %1}, %2;" : "=f"(f.x), "=f"(f.y) : "l"(v)); return f;
}

__global__ __launch_bounds__(NTHREADS, 2)
void node_rk4_kernel(const float* __restrict__ x,
                     const float* __restrict__ W1,
                     const float* __restrict__ b1,
                     const float* __restrict__ W2,
                     const float* __restrict__ b2,
                     float* __restrict__ out)
{
    extern __shared__ ull sm[];
    ull*   xdup = sm;                              // ROWS*F_DIM  (x dup pairs) 16KB
    float* xc   = (float*)(xdup + ROWS * F_DIM);   // ROWS*F_DIM  plain          8KB
    ull*   hdup = (ull*)(xc + ROWS * F_DIM);       // ROWS*H_DIM  (h dup pairs) 64KB

    const int tid = threadIdx.x;
    const int r0  = blockIdx.x * ROWS;

    // ---- init: load x block, emit out[0], fill xc/xdup ----
    for (int i = tid; i < ROWS * F_DIM; i += NTHREADS) {
        int row = i >> 8;
        int col = i & (F_DIM - 1);
        float v = x[(size_t)(r0 + row) * F_DIM + col];
        out[(size_t)(r0 + row) * F_DIM + col] = v;
        xc[row * F_DIM + col] = v;
        xdup[row * F_DIM + col] = pack2(v, v);
    }

    // ---- per-thread constants ----
    // GEMM1 cols: j = 4*tid + c
    const float* wtp = W1 + (size_t)F_DIM * H_DIM;
    const float4 wt4 = *((const float4*)wtp + tid);
    const float4 b14 = *((const float4*)b1 + tid);
    // GEMM2 tile: rows {2*rg, 2*rg+1}, cols {4*cg .. 4*cg+3}
    const int cg = tid & 63;
    const int rg = tid >> 6;
    const float4 b24 = *((const float4*)b2 + cg);

    const float dt  = 1.0f / 99.0f;
    const float dt6 = dt * (1.0f / 6.0f);

    float2 acc_rk[2][2];

    __syncthreads();

    const ulonglong2* wq1 = (const ulonglong2*)W1 + tid;  // row k -> wq1[k*256]
    const ulonglong2* wq2 = (const ulonglong2*)W2 + cg;   // row t -> wq2[t*64]

    for (int s = 0; s < NSTEPS - 1; ++s) {
        float t0 = (float)s * dt;
        #pragma unroll 1
        for (int e = 0; e < 4; ++e) {
            float te = t0 + ((e == 0) ? 0.0f : (e == 3) ? dt : 0.5f * dt);

            // ============ GEMM1: h = tanh(xe @ Wx + te*wt + b1) ============
            ull acc1[ROWS][2];
            #pragma unroll
            for (int r = 0; r < ROWS; ++r) { acc1[r][0] = 0ull; acc1[r][1] = 0ull; }

            ulonglong2 wa0 = __ldg(wq1 + 0 * 256);
            ulonglong2 wa1 = __ldg(wq1 + 1 * 256);
            ulonglong2 wb0 = __ldg(wq1 + 2 * 256);
            ulonglong2 wb1 = __ldg(wq1 + 3 * 256);

            #pragma unroll 1
            for (int k = 0; k < F_DIM; k += 4) {
                // compute k, k+1 with buffer A
                #pragma unroll
                for (int r = 0; r < ROWS; ++r) {
                    ulonglong2 xv = *(const ulonglong2*)&xdup[r * F_DIM + k];
                    fma2(acc1[r][0], xv.x, wa0.x);
                    fma2(acc1[r][1], xv.x, wa0.y);
                    fma2(acc1[r][0], xv.y, wa1.x);
                    fma2(acc1[r][1], xv.y, wa1.y);
                }
                int kp = (k + 4 < F_DIM) ? (k + 4) : (F_DIM - 4);
                wa0 = __ldg(wq1 + (size_t)kp * 256);
                wa1 = __ldg(wq1 + (size_t)(kp + 1) * 256);
                // compute k+2, k+3 with buffer B
                #pragma unroll
                for (int r = 0; r < ROWS; ++r) {
                    ulonglong2 xv = *(const ulonglong2*)&xdup[r * F_DIM + k + 2];
                    fma2(acc1[r][0], xv.x, wb0.x);
                    fma2(acc1[r][1], xv.x, wb0.y);
                    fma2(acc1[r][0], xv.y, wb1.x);
                    fma2(acc1[r][1], xv.y, wb1.y);
                }
                wb0 = __ldg(wq1 + (size_t)(kp + 2) * 256);
                wb1 = __ldg(wq1 + (size_t)(kp + 3) * 256);
            }

            // epilogue: bias + tanh, write duplicated hidden
            {
                float bias0 = fmaf(te, wt4.x, b14.x);
                float bias1 = fmaf(te, wt4.y, b14.y);
                float bias2 = fmaf(te, wt4.z, b14.z);
                float bias3 = fmaf(te, wt4.w, b14.w);
                #pragma unroll
                for (int r = 0; r < ROWS; ++r) {
                    float2 v0 = unpack2(acc1[r][0]);
                    float2 v1 = unpack2(acc1[r][1]);
                    float h0 = tanhf(v0.x + bias0);
                    float h1 = tanhf(v0.y + bias1);
                    float h2 = tanhf(v1.x + bias2);
                    float h3 = tanhf(v1.y + bias3);
                    ull* hp = &hdup[r * H_DIM + 4 * tid];
                    hp[0] = pack2(h0, h0);
                    hp[1] = pack2(h1, h1);
                    hp[2] = pack2(h2, h2);
                    hp[3] = pack2(h3, h3);
                }
            }
            __syncthreads();   // hdup visible before GEMM2

            // ============ GEMM2: kvec = h @ W2 + b2 ============
            ull acc2[2][2];
            acc2[0][0] = 0ull; acc2[0][1] = 0ull;
            acc2[1][0] = 0ull; acc2[1][1] = 0ull;

            const ull* h0p = &hdup[(2 * rg) * H_DIM];
            const ull* h1p = h0p + H_DIM;

            ulonglong2 va0 = __ldg(wq2 + 0 * 64);
            ulonglong2 va1 = __ldg(wq2 + 1 * 64);
            ulonglong2 vb0 = __ldg(wq2 + 2 * 64);
            ulonglong2 vb1 = __ldg(wq2 + 3 * 64);

            #pragma unroll 1
            for (int t = 0; t < H_DIM; t += 4) {
                // t, t+1 with buffer A
                {
                    ulonglong2 ha = *(const ulonglong2*)&h0p[t];
                    ulonglong2 hb = *(const ulonglong2*)&h1p[t];
                    fma2(acc2[0][0], ha.x, va0.x);
                    fma2(acc2[0][1], ha.x, va0.y);
                    fma2(acc2[1][0], hb.x, va0.x);
                    fma2(acc2[1][1], hb.x, va0.y);
                    fma2(acc2[0][0], ha.y, va1.x);
                    fma2(acc2[0][1], ha.y, va1.y);
                    fma2(acc2[1][0], hb.y, va1.x);
                    fma2(acc2[1][1], hb.y, va1.y);
                }
                int tp = (t + 4 < H_DIM) ? (t + 4) : (H_DIM - 4);
                va0 = __ldg(wq2 + (size_t)tp * 64);
                va1 = __ldg(wq2 + (size_t)(tp + 1) * 64);
                // t+2, t+3 with buffer B
                {
                    ulonglong2 ha = *(const ulonglong2*)&h0p[t + 2];
                    ulonglong2 hb = *(const ulonglong2*)&h1p[t + 2];
                    fma2(acc2[0][0], ha.x, vb0.x);
                    fma2(acc2[0][1], ha.x, vb0.y);
                    fma2(acc2[1][0], hb.x, vb0.x);
                    fma2(acc2[1][1], hb.x, vb0.y);
                    fma2(acc2[0][0], ha.y, vb1.x);
                    fma2(acc2[0][1], ha.y, vb1.y);
                    fma2(acc2[1][0], hb.y, vb1.x);
                    fma2(acc2[1][1], hb.y, vb1.y);
                }
                vb0 = __ldg(wq2 + (size_t)(tp + 2) * 64);
                vb1 = __ldg(wq2 + (size_t)(tp + 3) * 64);
            }

            // epilogue: RK4 state machine (thread-owned (2 rows x 4 cols) tile)
            float ae = (e == 3) ? 0.0f : ((e == 2) ? dt : 0.5f * dt);
            float be = (e == 1 || e == 2) ? 2.0f : 1.0f;
            #pragma unroll
            for (int i = 0; i < 2; ++i) {
                int row = 2 * rg + i;
                #pragma unroll
                for (int cp = 0; cp < 2; ++cp) {
                    float2 kv = unpack2(acc2[i][cp]);
                    kv.x += (cp == 0) ? b24.x : b24.z;
                    kv.y += (cp == 0) ? b24.y : b24.w;
                    if (e == 0) {
                        acc_rk[i][cp].x = kv.x;
                        acc_rk[i][cp].y = kv.y;
                    } else {
                        acc_rk[i][cp].x += be * kv.x;
                        acc_rk[i][cp].y += be * kv.y;
                    }
                    int col = 4 * cg + 2 * cp;
                    float2 xcv = *(const float2*)&xc[row * F_DIM + col];
                    float2 xe;
                    if (e < 3) {
                        xe.x = xcv.x + ae * kv.x;
                        xe.y = xcv.y + ae * kv.y;
                    } else {
                        xe.x = xcv.x + dt6 * acc_rk[i][cp].x;
                        xe.y = xcv.y + dt6 * acc_rk[i][cp].y;
                        *(float2*)&xc[row * F_DIM + col] = xe;
                        size_t ob = (size_t)(s + 1) * B_DIM * F_DIM;
                        *(float2*)&out[ob + (size_t)(r0 + row) * F_DIM + col] = xe;
                    }
                    xdup[row * F_DIM + col]     = pack2(xe.x, xe.x);
                    xdup[row * F_DIM + col + 1] = pack2(xe.y, xe.y);
                }
            }
            __syncthreads();   // xdup updated before next GEMM1
        }
    }
}

extern "C" void kernel_launch(void* const* d_in, const int* in_sizes, int n_in,
                              void* d_out, int out_size) {
    (void)in_sizes; (void)n_in; (void)out_size;
    const float* x  = (const float*)d_in[0];
    const float* W1 = (const float*)d_in[1];
    const float* b1 = (const float*)d_in[2];
    const float* W2 = (const float*)d_in[3];
    const float* b2 = (const float*)d_in[4];
    float* out = (float*)d_out;

    const size_t smem = (size_t)ROWS * F_DIM * 8     // xdup
                      + (size_t)ROWS * F_DIM * 4     // xc
                      + (size_t)ROWS * H_DIM * 8;    // hdup  => 88 KB
    cudaFuncSetAttribute(node_rk4_kernel,
                         cudaFuncAttributeMaxDynamicSharedMemorySize, (int)smem);
    node_rk4_kernel<<<NCTA, NTHREADS, smem>>>(x, W1, b1, W2, b2, out);
}

// round 4
// speedup vs baseline: 1.2800x; 1.2800x over previous
#include <cuda_runtime.h>

// NeuralODE RK4, round 4: 128 CTAs x 16 rows x 512 threads, 1 CTA/SM.
// Halves per-eval weight L2 traffic vs 256-CTA layouts. Both GEMMs consume
// weights straight from LDG.128 as f32x2 pairs (no pack MOVs); activations
// duplicated in SMEM with layouts tuned so LDS crossbar sits at ~50%.
// GEMM2 uses k-major hidden (stride-18 ull slices) + 2-way split-k.

#define B_DIM   2048
#define F_DIM   256
#define H_DIM   1024
#define NSTEPS  100
#define ROWS    16
#define NTHREADS 512
#define NCTA    (B_DIM / ROWS)   // 128
#define HSTRIDE 18               // ull per k-slice of hT (16 rows + 2 pad)

typedef unsigned long long ull;

__device__ __forceinline__ void fma2(ull &d, ull a, ull b) {
    asm("fma.rn.f32x2 %0, %1, %2, %0;" : "+l"(d) : "l"(a), "l"(b));
}
__device__ __forceinline__ ull add2(ull a, ull b) {
    ull r; asm("add.rn.f32x2 %0, %1, %2;" : "=l"(r) : "l"(a), "l"(b)); return r;
}
__device__ __forceinline__ ull pack2(float x, float y) {
    ull r; asm("mov.b64 %0, {%1, %2};" : "=l"(r) : "f"(x), "f"(y)); return r;
}
__device__ __forceinline__ float2 unpack2(ull v) {
    float2 f; asm("mov.b64 {%0, %1}, %2;" : "=f"(f.x), "=f"(f.y) : "l"(v)); return f;
}

__global__ __launch_bounds__(NTHREADS, 1)
void node_rk4_kernel(const float* __restrict__ x,
                     const float* __restrict__ W1,
                     const float* __restrict__ b1,
                     const float* __restrict__ W2,
                     const float* __restrict__ b2,
                     float* __restrict__ out)
{
    extern __shared__ ull sm[];
    ull*   xdup = sm;                           // 16*256 ull  = 32 KB (x, dup pairs)
    ull*   hT   = xdup + ROWS * F_DIM;          // 1024*18 ull = 144 KB (h, k-major, dup)
    ull*   red  = hT + H_DIM * HSTRIDE;         // 256*8 ull   = 16 KB (split-k partials)
    float* xc   = (float*)(red + 256 * 8);      // 16*256 f32  = 16 KB (base state)

    const int tid = threadIdx.x;
    const int r0  = blockIdx.x * ROWS;

    // ---- init: load x block, emit out slab 0, fill xc/xdup ----
    for (int i = tid; i < ROWS * F_DIM; i += NTHREADS) {
        int row = i >> 8;
        int col = i & (F_DIM - 1);
        float v = x[(size_t)(r0 + row) * F_DIM + col];
        out[(size_t)(r0 + row) * F_DIM + col] = v;
        xc[row * F_DIM + col] = v;
        xdup[row * F_DIM + col] = pack2(v, v);
    }

    // ---- GEMM1 mapping: rowgroup g (8 rows), cols 4c..4c+3 ----
    const int g = tid >> 8;          // 0..1
    const int c = tid & 255;         // 0..255
    const float4 wt4 = ((const float4*)(W1 + (size_t)F_DIM * H_DIM))[c];
    const float4 b14 = ((const float4*)b1)[c];

    // ---- GEMM2 mapping: split-k ks, rows 4rg..4rg+3, cols 4cg..4cg+3 ----
    const int ks = tid >> 8;         // 0..1 (k segment)
    const int rg = (tid >> 6) & 3;   // 0..3
    const int cg = tid & 63;         // 0..63
    const float4 b24 = ((const float4*)b2)[cg];

    const float dt  = 1.0f / 99.0f;
    const float dt6 = dt * (1.0f / 6.0f);

    float2 acc_rk[4][2];             // RK4 combined-k (ks==0 threads only)

    const ulonglong2* w1q = (const ulonglong2*)W1 + c;   // row k -> w1q[k*256]
    const ulonglong2* w2q = (const ulonglong2*)W2 + cg;  // row k -> w2q[k*64]

    __syncthreads();

    for (int s = 0; s < NSTEPS - 1; ++s) {
        float t0 = (float)s * dt;
        #pragma unroll 1
        for (int e = 0; e < 4; ++e) {
            float te = t0 + ((e == 0) ? 0.0f : (e == 3) ? dt : 0.5f * dt);

            // ============ GEMM1: h = tanh(xe @ Wx + te*wt + b1) ============
            ull acc1[8][2];
            #pragma unroll
            for (int r = 0; r < 8; ++r) { acc1[r][0] = 0ull; acc1[r][1] = 0ull; }

            const ull* xbase = xdup + g * 8 * F_DIM;
            ulonglong2 wa0 = __ldg(w1q + 0 * 256);
            ulonglong2 wa1 = __ldg(w1q + 1 * 256);
            ulonglong2 wb0 = __ldg(w1q + 2 * 256);
            ulonglong2 wb1 = __ldg(w1q + 3 * 256);

            #pragma unroll 1
            for (int k = 0; k < F_DIM; k += 4) {
                #pragma unroll
                for (int r = 0; r < 8; ++r) {
                    ulonglong2 xv = *(const ulonglong2*)(xbase + r * F_DIM + k);
                    fma2(acc1[r][0], xv.x, wa0.x);
                    fma2(acc1[r][1], xv.x, wa0.y);
                    fma2(acc1[r][0], xv.y, wa1.x);
                    fma2(acc1[r][1], xv.y, wa1.y);
                }
                int kp = (k + 4 < F_DIM) ? (k + 4) : (F_DIM - 4);
                wa0 = __ldg(w1q + (size_t)kp * 256);
                wa1 = __ldg(w1q + (size_t)(kp + 1) * 256);
                #pragma unroll
                for (int r = 0; r < 8; ++r) {
                    ulonglong2 xv = *(const ulonglong2*)(xbase + r * F_DIM + k + 2);
                    fma2(acc1[r][0], xv.x, wb0.x);
                    fma2(acc1[r][1], xv.x, wb0.y);
                    fma2(acc1[r][0], xv.y, wb1.x);
                    fma2(acc1[r][1], xv.y, wb1.y);
                }
                wb0 = __ldg(w1q + (size_t)(kp + 2) * 256);
                wb1 = __ldg(w1q + (size_t)(kp + 3) * 256);
            }

            // epilogue: bias + tanh, write k-major duplicated hidden
            {
                float bias[4] = { fmaf(te, wt4.x, b14.x), fmaf(te, wt4.y, b14.y),
                                  fmaf(te, wt4.z, b14.z), fmaf(te, wt4.w, b14.w) };
                #pragma unroll
                for (int jp = 0; jp < 2; ++jp) {
                    float hv[2][8];
                    #pragma unroll
                    for (int r = 0; r < 8; ++r) {
                        float2 v = unpack2(acc1[r][jp]);
                        hv[0][r] = tanhf(v.x + bias[2 * jp]);
                        hv[1][r] = tanhf(v.y + bias[2 * jp + 1]);
                    }
                    #pragma unroll
                    for (int sc = 0; sc < 2; ++sc) {
                        int j = 4 * c + 2 * jp + sc;
                        ull* dst = hT + (size_t)j * HSTRIDE + g * 8;
                        #pragma unroll
                        for (int r2 = 0; r2 < 4; ++r2) {
                            ulonglong2 val;
                            val.x = pack2(hv[sc][2 * r2],     hv[sc][2 * r2]);
                            val.y = pack2(hv[sc][2 * r2 + 1], hv[sc][2 * r2 + 1]);
                            *(ulonglong2*)(dst + 2 * r2) = val;
                        }
                    }
                }
            }
            __syncthreads();   // hT complete before GEMM2

            // ============ GEMM2: kvec = h @ W2 + b2  (2-way split-k) ============
            ull acc2[4][2];
            #pragma unroll
            for (int i = 0; i < 4; ++i) { acc2[i][0] = 0ull; acc2[i][1] = 0ull; }

            const int kb = ks * 512;
            const ull* hrow = hT + (size_t)kb * HSTRIDE + 4 * rg;
            ulonglong2 va0 = __ldg(w2q + (size_t)(kb + 0) * 64);
            ulonglong2 va1 = __ldg(w2q + (size_t)(kb + 1) * 64);
            ulonglong2 vb0 = __ldg(w2q + (size_t)(kb + 2) * 64);
            ulonglong2 vb1 = __ldg(w2q + (size_t)(kb + 3) * 64);

            #pragma unroll 1
            for (int kk = 0; kk < 512; kk += 4) {
                {   // kk, kk+1 with buffer A
                    ulonglong2 h01 = *(const ulonglong2*)(hrow);
                    ulonglong2 h23 = *(const ulonglong2*)(hrow + 2);
                    fma2(acc2[0][0], h01.x, va0.x); fma2(acc2[0][1], h01.x, va0.y);
                    fma2(acc2[1][0], h01.y, va0.x); fma2(acc2[1][1], h01.y, va0.y);
                    fma2(acc2[2][0], h23.x, va0.x); fma2(acc2[2][1], h23.x, va0.y);
                    fma2(acc2[3][0], h23.y, va0.x); fma2(acc2[3][1], h23.y, va0.y);
                    h01 = *(const ulonglong2*)(hrow + HSTRIDE);
                    h23 = *(const ulonglong2*)(hrow + HSTRIDE + 2);
                    fma2(acc2[0][0], h01.x, va1.x); fma2(acc2[0][1], h01.x, va1.y);
                    fma2(acc2[1][0], h01.y, va1.x); fma2(acc2[1][1], h01.y, va1.y);
                    fma2(acc2[2][0], h23.x, va1.x); fma2(acc2[2][1], h23.x, va1.y);
                    fma2(acc2[3][0], h23.y, va1.x); fma2(acc2[3][1], h23.y, va1.y);
                }
                int kp = (kk + 4 < 512) ? (kk + 4) : (512 - 4);
                va0 = __ldg(w2q + (size_t)(kb + kp) * 64);
                va1 = __ldg(w2q + (size_t)(kb + kp + 1) * 64);
                {   // kk+2, kk+3 with buffer B
                    ulonglong2 h01 = *(const ulonglong2*)(hrow + 2 * HSTRIDE);
                    ulonglong2 h23 = *(const ulonglong2*)(hrow + 2 * HSTRIDE + 2);
                    fma2(acc2[0][0], h01.x, vb0.x); fma2(acc2[0][1], h01.x, vb0.y);
                    fma2(acc2[1][0], h01.y, vb0.x); fma2(acc2[1][1], h01.y, vb0.y);
                    fma2(acc2[2][0], h23.x, vb0.x); fma2(acc2[2][1], h23.x, vb0.y);
                    fma2(acc2[3][0], h23.y, vb0.x); fma2(acc2[3][1], h23.y, vb0.y);
                    h01 = *(const ulonglong2*)(hrow + 3 * HSTRIDE);
                    h23 = *(const ulonglong2*)(hrow + 3 * HSTRIDE + 2);
                    fma2(acc2[0][0], h01.x, vb1.x); fma2(acc2[0][1], h01.x, vb1.y);
                    fma2(acc2[1][0], h01.y, vb1.x); fma2(acc2[1][1], h01.y, vb1.y);
                    fma2(acc2[2][0], h23.x, vb1.x); fma2(acc2[2][1], h23.x, vb1.y);
                    fma2(acc2[3][0], h23.y, vb1.x); fma2(acc2[3][1], h23.y, vb1.y);
                }
                vb0 = __ldg(w2q + (size_t)(kb + kp + 2) * 64);
                vb1 = __ldg(w2q + (size_t)(kb + kp + 3) * 64);
                hrow += 4 * HSTRIDE;
            }

            // split-k reduce: ks==1 publishes partials
            if (ks == 1) {
                ull* rp = red + (size_t)(tid & 255) * 8;
                #pragma unroll
                for (int i = 0; i < 4; ++i) {
                    ulonglong2 v; v.x = acc2[i][0]; v.y = acc2[i][1];
                    *(ulonglong2*)(rp + 2 * i) = v;
                }
            }
            __syncthreads();

            if (ks == 0) {
                const ull* rp = red + (size_t)tid * 8;
                #pragma unroll
                for (int i = 0; i < 4; ++i) {
                    ulonglong2 v = *(const ulonglong2*)(rp + 2 * i);
                    acc2[i][0] = add2(acc2[i][0], v.x);
                    acc2[i][1] = add2(acc2[i][1], v.y);
                }

                // RK4 epilogue: rows 4rg..4rg+3, cols 4cg..4cg+3
                float ae = (e == 3) ? 0.0f : ((e == 2) ? dt : 0.5f * dt);
                float be = (e == 1 || e == 2) ? 2.0f : 1.0f;
                size_t ob = (size_t)(s + 1) * B_DIM * F_DIM;
                #pragma unroll
                for (int i = 0; i < 4; ++i) {
                    int row = 4 * rg + i;
                    float xen[4];
                    #pragma unroll
                    for (int cp = 0; cp < 2; ++cp) {
                        float2 kv = unpack2(acc2[i][cp]);
                        kv.x += (cp == 0) ? b24.x : b24.z;
                        kv.y += (cp == 0) ? b24.y : b24.w;
                        if (e == 0) {
                            acc_rk[i][cp].x = kv.x;
                            acc_rk[i][cp].y = kv.y;
                        } else {
                            acc_rk[i][cp].x += be * kv.x;
                            acc_rk[i][cp].y += be * kv.y;
                        }
                        int col = 4 * cg + 2 * cp;
                        float2 xcv = *(const float2*)&xc[row * F_DIM + col];
                        if (e < 3) {
                            xen[2 * cp]     = xcv.x + ae * kv.x;
                            xen[2 * cp + 1] = xcv.y + ae * kv.y;
                        } else {
                            xen[2 * cp]     = xcv.x + dt6 * acc_rk[i][cp].x;
                            xen[2 * cp + 1] = xcv.y + dt6 * acc_rk[i][cp].y;
                        }
                    }
                    ull* xd = &xdup[row * F_DIM + 4 * cg];
                    ulonglong2 d0; d0.x = pack2(xen[0], xen[0]); d0.y = pack2(xen[1], xen[1]);
                    ulonglong2 d1; d1.x = pack2(xen[2], xen[2]); d1.y = pack2(xen[3], xen[3]);
                    *(ulonglong2*)(xd)     = d0;
                    *(ulonglong2*)(xd + 2) = d1;
                    if (e == 3) {
                        float4 xv4 = make_float4(xen[0], xen[1], xen[2], xen[3]);
                        *(float4*)&xc[row * F_DIM + 4 * cg] = xv4;
                        *(float4*)&out[ob + (size_t)(r0 + row) * F_DIM + 4 * cg] = xv4;
                    }
                }
            }
            __syncthreads();   // xdup stable before next GEMM1
        }
    }
}

extern "C" void kernel_launch(void* const* d_in, const int* in_sizes, int n_in,
                              void* d_out, int out_size) {
    (void)in_sizes; (void)n_in; (void)out_size;
    const float* x  = (const float*)d_in[0];
    const float* W1 = (const float*)d_in[1];
    const float* b1 = (const float*)d_in[2];
    const float* W2 = (const float*)d_in[3];
    const float* b2 = (const float*)d_in[4];
    float* out = (float*)d_out;

    const size_t smem = (size_t)ROWS * F_DIM * 8          // xdup 32 KB
                      + (size_t)H_DIM * HSTRIDE * 8       // hT  144 KB
                      + (size_t)256 * 8 * 8               // red  16 KB
                      + (size_t)ROWS * F_DIM * 4;         // xc   16 KB  => 208 KB
    cudaFuncSetAttribute(node_rk4_kernel,
                         cudaFuncAttributeMaxDynamicSharedMemorySize, (int)smem);
    node_rk4_kernel<<<NCTA, NTHREADS, smem>>>(x, W1, b1, W2, b2, out);
}

// round 5
// speedup vs baseline: 1.3660x; 1.0672x over previous
#include <cuda_runtime.h>

// NeuralODE RK4, round 5: 128 CTAs x 16 rows x 512 threads, 1 CTA/SM.
// GEMM2 re-mapped to 4-way split-k x 2 row-groups x 4 cols/thread: weight LDG
// duplication drops 8x -> 2x, L1 wavefronts/k drop 150% -> 100% of budget.
// Weights consumed raw from LDG.128 as col-pair f32x2 operands (zero packs).
// Split-k reduction via conflict-free SMEM buffer; RK4 epilogue on ks=0.

#define B_DIM   2048
#define F_DIM   256
#define H_DIM   1024
#define NSTEPS  100
#define ROWS    16
#define NTHREADS 512
#define NCTA    (B_DIM / ROWS)   // 128
#define HSTRIDE 18               // ull per k-slice of hT (16 rows + 2 pad)

typedef unsigned long long ull;

__device__ __forceinline__ void fma2(ull &d, ull a, ull b) {
    asm("fma.rn.f32x2 %0, %1, %2, %0;" : "+l"(d) : "l"(a), "l"(b));
}
__device__ __forceinline__ ull add2(ull a, ull b) {
    ull r; asm("add.rn.f32x2 %0, %1, %2;" : "=l"(r) : "l"(a), "l"(b)); return r;
}
__device__ __forceinline__ ull pack2(float x, float y) {
    ull r; asm("mov.b64 %0, {%1, %2};" : "=l"(r) : "f"(x), "f"(y)); return r;
}
__device__ __forceinline__ float2 unpack2(ull v) {
    float2 f; asm("mov.b64 {%0, %1}, %2;" : "=f"(f.x), "=f"(f.y) : "l"(v)); return f;
}

__global__ __launch_bounds__(NTHREADS, 1)
void node_rk4_kernel(const float* __restrict__ x,
                     const float* __restrict__ W1,
                     const float* __restrict__ b1,
                     const float* __restrict__ W2,
                     const float* __restrict__ b2,
                     float* __restrict__ out)
{
    extern __shared__ ull sm[];
    ull*   xdup = sm;                           // 16*256 ull  = 32 KB (x, dup pairs, row-major)
    ull*   hT   = xdup + ROWS * F_DIM;          // 1024*18 ull = 144 KB (h, k-major, dup)
    ull*   red  = hT + H_DIM * HSTRIDE;         // 4096 ull    = 32 KB (split-k partials)
    float* xc   = (float*)(red + 4096);         // 16*256 f32  = 16 KB (base state)

    const int tid = threadIdx.x;
    const int r0  = blockIdx.x * ROWS;

    // ---- init: load x block, emit out slab 0, fill xc/xdup ----
    for (int i = tid; i < ROWS * F_DIM; i += NTHREADS) {
        int row = i >> 8;
        int col = i & (F_DIM - 1);
        float v = x[(size_t)(r0 + row) * F_DIM + col];
        out[(size_t)(r0 + row) * F_DIM + col] = v;
        xc[row * F_DIM + col] = v;
        xdup[row * F_DIM + col] = pack2(v, v);
    }

    // ---- GEMM1 mapping: rowgroup g (8 rows), cols 4c..4c+3 ----
    const int g = tid >> 8;          // 0..1
    const int c = tid & 255;         // 0..255
    const float4 wt4 = ((const float4*)(W1 + (size_t)F_DIM * H_DIM))[c];
    const float4 b14 = ((const float4*)b1)[c];

    // ---- GEMM2 mapping: ks (k-quarter), rg (8-row group), cg (4 cols) ----
    const int ks = tid >> 7;         // 0..3
    const int rg = (tid >> 6) & 1;   // 0..1
    const int cg = tid & 63;         // 0..63
    const float4 b24 = ((const float4*)b2)[cg];

    const float dt  = 1.0f / 99.0f;
    const float dt6 = dt * (1.0f / 6.0f);

    float2 acc_rk[8][2];             // RK4 combined-k (ks==0 threads only)

    const ulonglong2* w1q = (const ulonglong2*)W1 + c;   // row k -> w1q[k*256]
    const ulonglong2* w2q = (const ulonglong2*)W2 + cg;  // row k -> w2q[k*64]
    ulonglong2* redq = (ulonglong2*)red;                 // [i(0..7)][slot(0..255)]

    __syncthreads();

    for (int s = 0; s < NSTEPS - 1; ++s) {
        float t0 = (float)s * dt;
        #pragma unroll 1
        for (int e = 0; e < 4; ++e) {
            float te = t0 + ((e == 0) ? 0.0f : (e == 3) ? dt : 0.5f * dt);

            // ============ GEMM1: h = tanh(xe @ Wx + te*wt + b1) ============
            ull acc1[8][2];
            #pragma unroll
            for (int r = 0; r < 8; ++r) { acc1[r][0] = 0ull; acc1[r][1] = 0ull; }

            const ull* xbase = xdup + g * 8 * F_DIM;
            ulonglong2 wa0 = __ldg(w1q + 0 * 256);
            ulonglong2 wa1 = __ldg(w1q + 1 * 256);
            ulonglong2 wb0 = __ldg(w1q + 2 * 256);
            ulonglong2 wb1 = __ldg(w1q + 3 * 256);

            #pragma unroll 1
            for (int k = 0; k < F_DIM; k += 4) {
                #pragma unroll
                for (int r = 0; r < 8; ++r) {
                    ulonglong2 xv = *(const ulonglong2*)(xbase + r * F_DIM + k);
                    fma2(acc1[r][0], xv.x, wa0.x);
                    fma2(acc1[r][1], xv.x, wa0.y);
                    fma2(acc1[r][0], xv.y, wa1.x);
                    fma2(acc1[r][1], xv.y, wa1.y);
                }
                int kp = (k + 4 < F_DIM) ? (k + 4) : (F_DIM - 4);
                wa0 = __ldg(w1q + (size_t)kp * 256);
                wa1 = __ldg(w1q + (size_t)(kp + 1) * 256);
                #pragma unroll
                for (int r = 0; r < 8; ++r) {
                    ulonglong2 xv = *(const ulonglong2*)(xbase + r * F_DIM + k + 2);
                    fma2(acc1[r][0], xv.x, wb0.x);
                    fma2(acc1[r][1], xv.x, wb0.y);
                    fma2(acc1[r][0], xv.y, wb1.x);
                    fma2(acc1[r][1], xv.y, wb1.y);
                }
                wb0 = __ldg(w1q + (size_t)(kp + 2) * 256);
                wb1 = __ldg(w1q + (size_t)(kp + 3) * 256);
            }

            // epilogue: bias + tanh, write k-major duplicated hidden
            {
                float bias[4] = { fmaf(te, wt4.x, b14.x), fmaf(te, wt4.y, b14.y),
                                  fmaf(te, wt4.z, b14.z), fmaf(te, wt4.w, b14.w) };
                #pragma unroll
                for (int jp = 0; jp < 2; ++jp) {
                    float hv[2][8];
                    #pragma unroll
                    for (int r = 0; r < 8; ++r) {
                        float2 v = unpack2(acc1[r][jp]);
                        hv[0][r] = tanhf(v.x + bias[2 * jp]);
                        hv[1][r] = tanhf(v.y + bias[2 * jp + 1]);
                    }
                    #pragma unroll
                    for (int sc = 0; sc < 2; ++sc) {
                        int j = 4 * c + 2 * jp + sc;
                        ull* dst = hT + (size_t)j * HSTRIDE + g * 8;
                        #pragma unroll
                        for (int r2 = 0; r2 < 4; ++r2) {
                            ulonglong2 val;
                            val.x = pack2(hv[sc][2 * r2],     hv[sc][2 * r2]);
                            val.y = pack2(hv[sc][2 * r2 + 1], hv[sc][2 * r2 + 1]);
                            *(ulonglong2*)(dst + 2 * r2) = val;
                        }
                    }
                }
            }
            __syncthreads();   // hT complete before GEMM2

            // ============ GEMM2: kvec = h @ W2 + b2  (4-way split-k) ============
            // thread tile: rows rg*8..rg*8+7, cols 4cg..4cg+3, k in [ks*256, ks*256+256)
            ull acc2[8][2];
            #pragma unroll
            for (int i = 0; i < 8; ++i) { acc2[i][0] = 0ull; acc2[i][1] = 0ull; }

            const int kb = ks * 256;
            const ull* hrow = hT + (size_t)kb * HSTRIDE + rg * 8;
            const ulonglong2* wp = w2q + (size_t)kb * 64;

            ulonglong2 va0 = __ldg(wp + 0 * 64);
            ulonglong2 va1 = __ldg(wp + 1 * 64);
            ulonglong2 vb0 = __ldg(wp + 2 * 64);
            ulonglong2 vb1 = __ldg(wp + 3 * 64);

            #pragma unroll 1
            for (int kk = 0; kk < 256; kk += 4) {
                {   // kk with va0
                    ulonglong2 h01 = *(const ulonglong2*)(hrow);
                    ulonglong2 h23 = *(const ulonglong2*)(hrow + 2);
                    ulonglong2 h45 = *(const ulonglong2*)(hrow + 4);
                    ulonglong2 h67 = *(const ulonglong2*)(hrow + 6);
                    fma2(acc2[0][0], h01.x, va0.x); fma2(acc2[0][1], h01.x, va0.y);
                    fma2(acc2[1][0], h01.y, va0.x); fma2(acc2[1][1], h01.y, va0.y);
                    fma2(acc2[2][0], h23.x, va0.x); fma2(acc2[2][1], h23.x, va0.y);
                    fma2(acc2[3][0], h23.y, va0.x); fma2(acc2[3][1], h23.y, va0.y);
                    fma2(acc2[4][0], h45.x, va0.x); fma2(acc2[4][1], h45.x, va0.y);
                    fma2(acc2[5][0], h45.y, va0.x); fma2(acc2[5][1], h45.y, va0.y);
                    fma2(acc2[6][0], h67.x, va0.x); fma2(acc2[6][1], h67.x, va0.y);
                    fma2(acc2[7][0], h67.y, va0.x); fma2(acc2[7][1], h67.y, va0.y);
                }
                {   // kk+1 with va1
                    ulonglong2 h01 = *(const ulonglong2*)(hrow + HSTRIDE);
                    ulonglong2 h23 = *(const ulonglong2*)(hrow + HSTRIDE + 2);
                    ulonglong2 h45 = *(const ulonglong2*)(hrow + HSTRIDE + 4);
                    ulonglong2 h67 = *(const ulonglong2*)(hrow + HSTRIDE + 6);
                    fma2(acc2[0][0], h01.x, va1.x); fma2(acc2[0][1], h01.x, va1.y);
                    fma2(acc2[1][0], h01.y, va1.x); fma2(acc2[1][1], h01.y, va1.y);
                    fma2(acc2[2][0], h23.x, va1.x); fma2(acc2[2][1], h23.x, va1.y);
                    fma2(acc2[3][0], h23.y, va1.x); fma2(acc2[3][1], h23.y, va1.y);
                    fma2(acc2[4][0], h45.x, va1.x); fma2(acc2[4][1], h45.x, va1.y);
                    fma2(acc2[5][0], h45.y, va1.x); fma2(acc2[5][1], h45.y, va1.y);
                    fma2(acc2[6][0], h67.x, va1.x); fma2(acc2[6][1], h67.x, va1.y);
                    fma2(acc2[7][0], h67.y, va1.x); fma2(acc2[7][1], h67.y, va1.y);
                }
                int kp = (kk + 4 < 256) ? (kk + 4) : 252;
                va0 = __ldg(wp + (size_t)kp * 64);
                va1 = __ldg(wp + (size_t)(kp + 1) * 64);
                {   // kk+2 with vb0
                    ulonglong2 h01 = *(const ulonglong2*)(hrow + 2 * HSTRIDE);
                    ulonglong2 h23 = *(const ulonglong2*)(hrow + 2 * HSTRIDE + 2);
                    ulonglong2 h45 = *(const ulonglong2*)(hrow + 2 * HSTRIDE + 4);
                    ulonglong2 h67 = *(const ulonglong2*)(hrow + 2 * HSTRIDE + 6);
                    fma2(acc2[0][0], h01.x, vb0.x); fma2(acc2[0][1], h01.x, vb0.y);
                    fma2(acc2[1][0], h01.y, vb0.x); fma2(acc2[1][1], h01.y, vb0.y);
                    fma2(acc2[2][0], h23.x, vb0.x); fma2(acc2[2][1], h23.x, vb0.y);
                    fma2(acc2[3][0], h23.y, vb0.x); fma2(acc2[3][1], h23.y, vb0.y);
                    fma2(acc2[4][0], h45.x, vb0.x); fma2(acc2[4][1], h45.x, vb0.y);
                    fma2(acc2[5][0], h45.y, vb0.x); fma2(acc2[5][1], h45.y, vb0.y);
                    fma2(acc2[6][0], h67.x, vb0.x); fma2(acc2[6][1], h67.x, vb0.y);
                    fma2(acc2[7][0], h67.y, vb0.x); fma2(acc2[7][1], h67.y, vb0.y);
                }
                {   // kk+3 with vb1
                    ulonglong2 h01 = *(const ulonglong2*)(hrow + 3 * HSTRIDE);
                    ulonglong2 h23 = *(const ulonglong2*)(hrow + 3 * HSTRIDE + 2);
                    ulonglong2 h45 = *(const ulonglong2*)(hrow + 3 * HSTRIDE + 4);
                    ulonglong2 h67 = *(const ulonglong2*)(hrow + 3 * HSTRIDE + 6);
                    fma2(acc2[0][0], h01.x, vb1.x); fma2(acc2[0][1], h01.x, vb1.y);
                    fma2(acc2[1][0], h01.y, vb1.x); fma2(acc2[1][1], h01.y, vb1.y);
                    fma2(acc2[2][0], h23.x, vb1.x); fma2(acc2[2][1], h23.x, vb1.y);
                    fma2(acc2[3][0], h23.y, vb1.x); fma2(acc2[3][1], h23.y, vb1.y);
                    fma2(acc2[4][0], h45.x, vb1.x); fma2(acc2[4][1], h45.x, vb1.y);
                    fma2(acc2[5][0], h45.y, vb1.x); fma2(acc2[5][1], h45.y, vb1.y);
                    fma2(acc2[6][0], h67.x, vb1.x); fma2(acc2[6][1], h67.x, vb1.y);
                    fma2(acc2[7][0], h67.y, vb1.x); fma2(acc2[7][1], h67.y, vb1.y);
                }
                vb0 = __ldg(wp + (size_t)(kp + 2) * 64);
                vb1 = __ldg(wp + (size_t)(kp + 3) * 64);
                hrow += 4 * HSTRIDE;
            }

            // ---- split-k reduction ----
            // slot = (rg*64 + cg) + 128*(group): redq[i*256 + slot] (conflict-free: i-major)
            const int slot = tid & 127;
            if (ks >= 2) {
                int base = (ks - 2) * 128 + slot;
                #pragma unroll
                for (int i = 0; i < 8; ++i) {
                    ulonglong2 v; v.x = acc2[i][0]; v.y = acc2[i][1];
                    redq[i * 256 + base] = v;
                }
            }
            __syncthreads();
            if (ks == 0) {
                #pragma unroll
                for (int i = 0; i < 8; ++i) {
                    ulonglong2 v = redq[i * 256 + slot];        // ks2 partial
                    acc2[i][0] = add2(acc2[i][0], v.x);
                    acc2[i][1] = add2(acc2[i][1], v.y);
                }
            } else if (ks == 1) {
                #pragma unroll
                for (int i = 0; i < 8; ++i) {
                    int idx = i * 256 + 128 + slot;              // ks3 partial
                    ulonglong2 v = redq[idx];
                    v.x = add2(acc2[i][0], v.x);
                    v.y = add2(acc2[i][1], v.y);
                    redq[idx] = v;                               // publish ks1+ks3 sum
                }
            }
            __syncthreads();

            if (ks == 0) {
                #pragma unroll
                for (int i = 0; i < 8; ++i) {
                    ulonglong2 v = redq[i * 256 + 128 + slot];   // ks1+ks3 sum
                    acc2[i][0] = add2(acc2[i][0], v.x);
                    acc2[i][1] = add2(acc2[i][1], v.y);
                }

                // ---- RK4 epilogue: rows rg*8..rg*8+7, cols 4cg..4cg+3 ----
                float ae = (e == 3) ? 0.0f : ((e == 2) ? dt : 0.5f * dt);
                float be = (e == 1 || e == 2) ? 2.0f : 1.0f;
                size_t ob = (size_t)(s + 1) * B_DIM * F_DIM;
                #pragma unroll
                for (int i = 0; i < 8; ++i) {
                    int row = rg * 8 + i;
                    float xen[4];
                    #pragma unroll
                    for (int cp = 0; cp < 2; ++cp) {
                        float2 kv = unpack2(acc2[i][cp]);
                        kv.x += (cp == 0) ? b24.x : b24.z;
                        kv.y += (cp == 0) ? b24.y : b24.w;
                        if (e == 0) {
                            acc_rk[i][cp].x = kv.x;
                            acc_rk[i][cp].y = kv.y;
                        } else {
                            acc_rk[i][cp].x += be * kv.x;
                            acc_rk[i][cp].y += be * kv.y;
                        }
                        int col = 4 * cg + 2 * cp;
                        float2 xcv = *(const float2*)&xc[row * F_DIM + col];
                        if (e < 3) {
                            xen[2 * cp]     = xcv.x + ae * kv.x;
                            xen[2 * cp + 1] = xcv.y + ae * kv.y;
                        } else {
                            xen[2 * cp]     = xcv.x + dt6 * acc_rk[i][cp].x;
                            xen[2 * cp + 1] = xcv.y + dt6 * acc_rk[i][cp].y;
                        }
                    }
                    ull* xd = &xdup[row * F_DIM + 4 * cg];
                    ulonglong2 d0; d0.x = pack2(xen[0], xen[0]); d0.y = pack2(xen[1], xen[1]);
                    ulonglong2 d1; d1.x = pack2(xen[2], xen[2]); d1.y = pack2(xen[3], xen[3]);
                    *(ulonglong2*)(xd)     = d0;
                    *(ulonglong2*)(xd + 2) = d1;
                    if (e == 3) {
                        float4 xv4 = make_float4(xen[0], xen[1], xen[2], xen[3]);
                        *(float4*)&xc[row * F_DIM + 4 * cg] = xv4;
                        *(float4*)&out[ob + (size_t)(r0 + row) * F_DIM + 4 * cg] = xv4;
                    }
                }
            }
            __syncthreads();   // xdup stable before next GEMM1
        }
    }
}

extern "C" void kernel_launch(void* const* d_in, const int* in_sizes, int n_in,
                              void* d_out, int out_size) {
    (void)in_sizes; (void)n_in; (void)out_size;
    const float* x  = (const float*)d_in[0];
    const float* W1 = (const float*)d_in[1];
    const float* b1 = (const float*)d_in[2];
    const float* W2 = (const float*)d_in[3];
    const float* b2 = (const float*)d_in[4];
    float* out = (float*)d_out;

    const size_t smem = (size_t)ROWS * F_DIM * 8          // xdup 32 KB
                      + (size_t)H_DIM * HSTRIDE * 8       // hT  144 KB
                      + (size_t)4096 * 8                  // red  32 KB
                      + (size_t)ROWS * F_DIM * 4;         // xc   16 KB  => 224 KB
    cudaFuncSetAttribute(node_rk4_kernel,
                         cudaFuncAttributeMaxDynamicSharedMemorySize, (int)smem);
    node_rk4_kernel<<<NCTA, NTHREADS, smem>>>(x, W1, b1, W2, b2, out);
}

// round 7
// speedup vs baseline: 1.9947x; 1.4602x over previous
#include <cuda_runtime.h>
#include <cuda_bf16.h>
#include <stdint.h>

// NeuralODE RK4 via legacy-path bf16 tensor cores (mma.sync m16n8k16), since
// the bench targets plain sm_103 (no 'a' => no tcgen05). Exact 2-way bf16
// split of activations AND weights; 3 accumulating component passes
// (c0w0, c1w0, c0w1) give ~2^-18 per-product error -> rel_err ~1e-5.
// Per eval: k_gemm1 (128 CTAs, 128x128 tile) then k_gemm2+RK4 (64 CTAs,
// 64x128 tile). cp.async double-buffered smem, ldmatrix, swizzled tiles.

typedef unsigned int u32;
typedef unsigned long long u64;

#define B_DIM 2048
#define F_DIM 256
#define H_DIM 1024

// split planes (bf16, row-major)
__device__ __nv_bfloat16 gA0[B_DIM * F_DIM];     // xe hi
__device__ __nv_bfloat16 gA1[B_DIM * F_DIM];     // xe lo
__device__ __nv_bfloat16 gH0[B_DIM * H_DIM];     // h  hi
__device__ __nv_bfloat16 gH1[B_DIM * H_DIM];     // h  lo
__device__ __nv_bfloat16 gW1a[F_DIM * H_DIM];    // W1 body hi  [k][n]
__device__ __nv_bfloat16 gW1b[F_DIM * H_DIM];    // W1 body lo
__device__ __nv_bfloat16 gW2a[H_DIM * F_DIM];    // W2 hi       [k][n]
__device__ __nv_bfloat16 gW2b[H_DIM * F_DIM];    // W2 lo
__device__ float g_xc [B_DIM * F_DIM];           // RK4 base state
__device__ float g_acc[B_DIM * F_DIM];           // RK4 k-accumulator

__device__ __forceinline__ u32 s2u(const void* p) {
    u32 a;
    asm("{ .reg .u64 t; cvta.to.shared.u64 t, %1; cvt.u32.u64 %0, t; }" : "=r"(a) : "l"(p));
    return a;
}
__device__ __forceinline__ void split2(float v, uint16_t& hi, uint16_t& lo) {
    __nv_bfloat16 b0 = __float2bfloat16_rn(v);
    float r = v - __bfloat162float(b0);
    __nv_bfloat16 b1 = __float2bfloat16_rn(r);
    hi = __nv_bfloat16_raw(b0).x;
    lo = __nv_bfloat16_raw(b1).x;
}
__device__ __forceinline__ void cpa16(u32 dst, const void* src) {
    asm volatile("cp.async.cg.shared.global [%0], [%1], 16;" :: "r"(dst), "l"(src));
}
__device__ __forceinline__ void cpa_commit() { asm volatile("cp.async.commit_group;" ::: "memory"); }
__device__ __forceinline__ void cpwait1() { asm volatile("cp.async.wait_group 1;" ::: "memory"); }
__device__ __forceinline__ void cpwait0() { asm volatile("cp.async.wait_group 0;" ::: "memory"); }

__device__ __forceinline__ void ldsm_a(u32 addr, u32& r0, u32& r1, u32& r2, u32& r3) {
    asm volatile("ldmatrix.sync.aligned.m8n8.x4.shared.b16 {%0,%1,%2,%3}, [%4];"
                 : "=r"(r0), "=r"(r1), "=r"(r2), "=r"(r3) : "r"(addr));
}
__device__ __forceinline__ void ldsm_bt(u32 addr, u32& r0, u32& r1, u32& r2, u32& r3) {
    asm volatile("ldmatrix.sync.aligned.m8n8.x4.trans.shared.b16 {%0,%1,%2,%3}, [%4];"
                 : "=r"(r0), "=r"(r1), "=r"(r2), "=r"(r3) : "r"(addr));
}
__device__ __forceinline__ void mma16816(float* c, u32 a0, u32 a1, u32 a2, u32 a3,
                                         u32 b0, u32 b1) {
    asm volatile(
        "mma.sync.aligned.m16n8k16.row.col.f32.bf16.bf16.f32 "
        "{%0,%1,%2,%3}, {%4,%5,%6,%7}, {%8,%9}, {%0,%1,%2,%3};"
        : "+f"(c[0]), "+f"(c[1]), "+f"(c[2]), "+f"(c[3])
        : "r"(a0), "r"(a1), "r"(a2), "r"(a3), "r"(b0), "r"(b1));
}

// ---------------- setup ----------------

__global__ void k_conv(const float* __restrict__ W1, const float* __restrict__ W2) {
    int i = blockIdx.x * blockDim.x + threadIdx.x;
    uint16_t a, b;
    if (i < F_DIM * H_DIM) {                 // W1 body rows 0..255 (row-major [257][1024])
        split2(W1[i], a, b);
        ((uint16_t*)gW1a)[i] = a;
        ((uint16_t*)gW1b)[i] = b;
    } else if (i < 2 * F_DIM * H_DIM) {
        int j = i - F_DIM * H_DIM;
        split2(W2[j], a, b);
        ((uint16_t*)gW2a)[j] = a;
        ((uint16_t*)gW2b)[j] = b;
    }
}

__global__ void k_init(const float* __restrict__ x, float* __restrict__ out) {
    int i = blockIdx.x * blockDim.x + threadIdx.x;
    if (i >= B_DIM * F_DIM) return;
    float v = x[i];
    out[i] = v;                              // slab 0
    g_xc[i] = v;
    uint16_t a, b; split2(v, a, b);
    ((uint16_t*)gA0)[i] = a;
    ((uint16_t*)gA1)[i] = b;
}

// component pass tables: (A-plane, B-plane) per pass
__device__ __constant__ int cPA[3] = {0, 1, 0};
__device__ __constant__ int cPB[3] = {0, 0, 1};

// ---------------- GEMM1: h = tanh(xe @ W1x + te*wt + b1) ----------------
// grid (16, 8): CTA 128x128, K_eff = 3*256 in 12 chunks of 64.

__global__ __launch_bounds__(256, 2) void k_gemm1(const float* __restrict__ b1,
                                                  const float* __restrict__ wt,
                                                  float te) {
    extern __shared__ __align__(128) unsigned char smem[];
    const u32 sb = s2u(smem);
    const int tid = threadIdx.x, lane = tid & 31, wid = tid >> 5;
    const int wm = wid & 1, wn = wid >> 1;            // warp grid 2 x 4
    const int m0 = blockIdx.x * 128, n0 = blockIdx.y * 128;

    const __nv_bfloat16* Apl[2] = {gA0, gA1};
    const __nv_bfloat16* Bpl[2] = {gW1a, gW1b};

    float acc[4][4][4];
    #pragma unroll
    for (int i = 0; i < 4; ++i)
        #pragma unroll
        for (int j = 0; j < 4; ++j)
            #pragma unroll
            for (int q = 0; q < 4; ++q) acc[i][j][q] = 0.0f;

    auto issue = [&](int c) {
        int p  = c >> 2;                 // 4 chunks per pass
        int ko = (c & 3) * 64;
        const __nv_bfloat16* Ap = Apl[cPA[p]];
        const __nv_bfloat16* Bp = Bpl[cPB[p]];
        u32 st = sb + (u32)(c & 1) * 32768u;
        #pragma unroll
        for (int t = 0; t < 4; ++t) {            // A tile 128x64 (16 KB)
            int cc = tid + t * 256;
            int r = cc >> 3, col = cc & 7;
            u32 dst = st + (u32)r * 128 + (u32)((col ^ (r & 7)) << 4);
            cpa16(dst, Ap + (size_t)(m0 + r) * F_DIM + ko + col * 8);
        }
        #pragma unroll
        for (int t = 0; t < 4; ++t) {            // B tile 64x128 (16 KB)
            int cc = tid + t * 256;
            int r = cc >> 4, col = cc & 15;
            u32 dst = st + 16384 + (u32)r * 256 + (u32)((col ^ (r & 7)) << 4);
            cpa16(dst, Bp + (size_t)(ko + r) * H_DIM + n0 + col * 8);
        }
        cpa_commit();
    };

    const int lr  = (lane & 7) + ((lane >> 3) & 1) * 8;
    const int hk  = lane >> 4;
    const int ar0 = wm * 64 + lr;
    const int asw = ar0 & 7;
    const int bsw = lr & 7;

    issue(0);
    #pragma unroll 1
    for (int c = 0; c < 12; ++c) {
        if (c + 1 < 12) { issue(c + 1); cpwait1(); } else { cpwait0(); }
        __syncthreads();
        u32 ast = sb + (u32)(c & 1) * 32768u;
        u32 bst = ast + 16384;
        #pragma unroll
        for (int ks = 0; ks < 4; ++ks) {
            u32 a[4][4];
            #pragma unroll
            for (int mi = 0; mi < 4; ++mi) {
                u32 ad = ast + (u32)(ar0 + mi * 16) * 128 + (u32)((((ks << 1) + hk) ^ asw) << 4);
                ldsm_a(ad, a[mi][0], a[mi][1], a[mi][2], a[mi][3]);
            }
            u32 b[4][2];
            #pragma unroll
            for (int nbp = 0; nbp < 2; ++nbp) {
                int row = ks * 16 + lr;
                int nblk = wn * 4 + nbp * 2 + hk;
                u32 bd = bst + (u32)row * 256 + (u32)((nblk ^ bsw) << 4);
                ldsm_bt(bd, b[nbp * 2][0], b[nbp * 2][1], b[nbp * 2 + 1][0], b[nbp * 2 + 1][1]);
            }
            #pragma unroll
            for (int mi = 0; mi < 4; ++mi)
                #pragma unroll
                for (int nb = 0; nb < 4; ++nb)
                    mma16816(acc[mi][nb], a[mi][0], a[mi][1], a[mi][2], a[mi][3],
                             b[nb][0], b[nb][1]);
        }
        __syncthreads();
    }

    // epilogue: bias + te*wt, tanh, split-2 -> H planes
    const int rbase = m0 + wm * 64 + (lane >> 2);
    const int cbase = n0 + wn * 32 + (lane & 3) * 2;
    #pragma unroll
    for (int nb = 0; nb < 4; ++nb) {
        int j = cbase + nb * 8;
        float2 bb = *(const float2*)(b1 + j);
        float2 ww = *(const float2*)(wt + j);
        float bias0 = bb.x + te * ww.x;
        float bias1 = bb.y + te * ww.y;
        #pragma unroll
        for (int mi = 0; mi < 4; ++mi) {
            #pragma unroll
            for (int h = 0; h < 2; ++h) {
                int row = rbase + mi * 16 + h * 8;
                float v0 = tanhf(acc[mi][nb][h * 2]     + bias0);
                float v1 = tanhf(acc[mi][nb][h * 2 + 1] + bias1);
                uint16_t h0, l0, h1, l1;
                split2(v0, h0, l0); split2(v1, h1, l1);
                size_t o = ((size_t)row * H_DIM + j) >> 1;
                ((u32*)gH0)[o] = (u32)h0 | ((u32)h1 << 16);
                ((u32*)gH1)[o] = (u32)l0 | ((u32)l1 << 16);
            }
        }
    }
}

// ---------------- GEMM2 + RK4: k = h @ W2 + b2 ----------------
// grid (32, 2): CTA 64x128, K_eff = 3*1024 in 48 chunks of 64.

__global__ __launch_bounds__(256, 2) void k_gemm2(const float* __restrict__ b2,
                                                  float* __restrict__ out,
                                                  int e, int s, float ae) {
    extern __shared__ __align__(128) unsigned char smem[];
    const u32 sb = s2u(smem);
    const int tid = threadIdx.x, lane = tid & 31, wid = tid >> 5;
    const int wm = wid & 1, wn = wid >> 1;            // warp grid 2 x 4 (32x32 tiles)
    const int m0 = blockIdx.x * 64, n0 = blockIdx.y * 128;

    const __nv_bfloat16* Apl[2] = {gH0, gH1};
    const __nv_bfloat16* Bpl[2] = {gW2a, gW2b};

    float acc[2][4][4];
    #pragma unroll
    for (int i = 0; i < 2; ++i)
        #pragma unroll
        for (int j = 0; j < 4; ++j)
            #pragma unroll
            for (int q = 0; q < 4; ++q) acc[i][j][q] = 0.0f;

    auto issue = [&](int c) {
        int p  = c >> 4;                 // 16 chunks per pass
        int ko = (c & 15) * 64;
        const __nv_bfloat16* Ap = Apl[cPA[p]];
        const __nv_bfloat16* Bp = Bpl[cPB[p]];
        u32 st = sb + (u32)(c & 1) * 24576u;
        #pragma unroll
        for (int t = 0; t < 2; ++t) {            // A tile 64x64 (8 KB)
            int cc = tid + t * 256;
            int r = cc >> 3, col = cc & 7;
            u32 dst = st + (u32)r * 128 + (u32)((col ^ (r & 7)) << 4);
            cpa16(dst, Ap + (size_t)(m0 + r) * H_DIM + ko + col * 8);
        }
        #pragma unroll
        for (int t = 0; t < 4; ++t) {            // B tile 64x128 (16 KB)
            int cc = tid + t * 256;
            int r = cc >> 4, col = cc & 15;
            u32 dst = st + 8192 + (u32)r * 256 + (u32)((col ^ (r & 7)) << 4);
            cpa16(dst, Bp + (size_t)(ko + r) * F_DIM + n0 + col * 8);
        }
        cpa_commit();
    };

    const int lr  = (lane & 7) + ((lane >> 3) & 1) * 8;
    const int hk  = lane >> 4;
    const int ar0 = wm * 32 + lr;
    const int asw = ar0 & 7;
    const int bsw = lr & 7;

    issue(0);
    #pragma unroll 1
    for (int c = 0; c < 48; ++c) {
        if (c + 1 < 48) { issue(c + 1); cpwait1(); } else { cpwait0(); }
        __syncthreads();
        u32 ast = sb + (u32)(c & 1) * 24576u;
        u32 bst = ast + 8192;
        #pragma unroll
        for (int ks = 0; ks < 4; ++ks) {
            u32 a[2][4];
            #pragma unroll
            for (int mi = 0; mi < 2; ++mi) {
                u32 ad = ast + (u32)(ar0 + mi * 16) * 128 + (u32)((((ks << 1) + hk) ^ asw) << 4);
                ldsm_a(ad, a[mi][0], a[mi][1], a[mi][2], a[mi][3]);
            }
            u32 b[4][2];
            #pragma unroll
            for (int nbp = 0; nbp < 2; ++nbp) {
                int row = ks * 16 + lr;
                int nblk = wn * 4 + nbp * 2 + hk;
                u32 bd = bst + (u32)row * 256 + (u32)((nblk ^ bsw) << 4);
                ldsm_bt(bd, b[nbp * 2][0], b[nbp * 2][1], b[nbp * 2 + 1][0], b[nbp * 2 + 1][1]);
            }
            #pragma unroll
            for (int mi = 0; mi < 2; ++mi)
                #pragma unroll
                for (int nb = 0; nb < 4; ++nb)
                    mma16816(acc[mi][nb], a[mi][0], a[mi][1], a[mi][2], a[mi][3],
                             b[nb][0], b[nb][1]);
        }
        __syncthreads();
    }

    // epilogue: RK4 state machine
    const float dt6 = (1.0f / 99.0f) / 6.0f;
    const float be = (e == 1 || e == 2) ? 2.0f : 1.0f;
    const int rbase = m0 + wm * 32 + (lane >> 2);
    const int cbase = n0 + wn * 32 + (lane & 3) * 2;
    #pragma unroll
    for (int nb = 0; nb < 4; ++nb) {
        int j = cbase + nb * 8;
        float2 bb = *(const float2*)(b2 + j);
        #pragma unroll
        for (int mi = 0; mi < 2; ++mi) {
            #pragma unroll
            for (int h = 0; h < 2; ++h) {
                int row = rbase + mi * 16 + h * 8;
                size_t go = (size_t)row * F_DIM + j;
                float kv0 = acc[mi][nb][h * 2]     + bb.x;
                float kv1 = acc[mi][nb][h * 2 + 1] + bb.y;
                float2 xcv = *(const float2*)&g_xc[go];
                float a0, a1;
                if (e == 0) { a0 = kv0; a1 = kv1; }
                else {
                    float2 av = *(const float2*)&g_acc[go];
                    a0 = av.x + be * kv0; a1 = av.y + be * kv1;
                }
                float x0, x1;
                if (e < 3) {
                    x0 = xcv.x + ae * kv0; x1 = xcv.y + ae * kv1;
                    *(float2*)&g_acc[go] = make_float2(a0, a1);
                } else {
                    x0 = xcv.x + dt6 * a0; x1 = xcv.y + dt6 * a1;
                    *(float2*)&g_xc[go] = make_float2(x0, x1);
                    *(float2*)&out[(size_t)(s + 1) * B_DIM * F_DIM + go] = make_float2(x0, x1);
                }
                uint16_t h0, l0, h1, l1;
                split2(x0, h0, l0); split2(x1, h1, l1);
                ((u32*)gA0)[go >> 1] = (u32)h0 | ((u32)h1 << 16);
                ((u32*)gA1)[go >> 1] = (u32)l0 | ((u32)l1 << 16);
            }
        }
    }
}

// ---------------- host ----------------

extern "C" void kernel_launch(void* const* d_in, const int* in_sizes, int n_in,
                              void* d_out, int out_size) {
    (void)in_sizes; (void)n_in; (void)out_size;
    const float* x  = (const float*)d_in[0];
    const float* W1 = (const float*)d_in[1];
    const float* b1 = (const float*)d_in[2];
    const float* W2 = (const float*)d_in[3];
    const float* b2 = (const float*)d_in[4];
    float* out = (float*)d_out;

    cudaFuncSetAttribute(k_gemm1, cudaFuncAttributeMaxDynamicSharedMemorySize, 65536);
    cudaFuncSetAttribute(k_gemm2, cudaFuncAttributeMaxDynamicSharedMemorySize, 49152);

    k_conv<<<2048, 256>>>(W1, W2);
    k_init<<<2048, 256>>>(x, out);

    const float dt = 1.0f / 99.0f;
    const float* wt = W1 + (size_t)F_DIM * H_DIM;    // time row of W1
    for (int s = 0; s < 99; ++s) {
        float t0 = s * dt;
        const float te_arr[4] = {t0, t0 + 0.5f * dt, t0 + 0.5f * dt, t0 + dt};
        const float ae_arr[4] = {0.5f * dt, 0.5f * dt, dt, 0.0f};
        for (int e = 0; e < 4; ++e) {
            k_gemm1<<<dim3(16, 8), 256, 65536>>>(b1, wt, te_arr[e]);
            k_gemm2<<<dim3(32, 2), 256, 49152>>>(b2, out, e, s, ae_arr[e]);
        }
    }
}

// round 9
// speedup vs baseline: 3.2384x; 1.6235x over previous
#include <cuda_runtime.h>
#include <cuda_bf16.h>
#include <stdint.h>

// NeuralODE RK4, round 9: bf16 mma.sync, exact 2-way split, PASS-FUSED chunks
// (both planes loaded once per chunk, 3 mma combos). Back to 2 kernels/eval
// (794 graph nodes — the 3-kernel/1190-node variant tripped the harness's
// post-teardown memory check). GEMM2 owns its output tile -> RK4 epilogue
// fused, no partials buffer.

typedef unsigned int u32;

#define B_DIM 2048
#define F_DIM 256
#define H_DIM 1024
#define BF    (B_DIM * F_DIM)

__device__ __nv_bfloat16 gA0[BF];                // xe hi
__device__ __nv_bfloat16 gA1[BF];                // xe lo
__device__ __nv_bfloat16 gH0[B_DIM * H_DIM];     // h  hi
__device__ __nv_bfloat16 gH1[B_DIM * H_DIM];     // h  lo
__device__ __nv_bfloat16 gW1a[F_DIM * H_DIM];    // W1 body hi [k][n]
__device__ __nv_bfloat16 gW1b[F_DIM * H_DIM];    // W1 body lo
__device__ __nv_bfloat16 gW2a[H_DIM * F_DIM];    // W2 hi      [k][n]
__device__ __nv_bfloat16 gW2b[H_DIM * F_DIM];    // W2 lo
__device__ float g_xc [BF];                      // RK4 base state
__device__ float g_acc[BF];                      // RK4 k-accumulator

__device__ __forceinline__ u32 s2u(const void* p) {
    u32 a;
    asm("{ .reg .u64 t; cvta.to.shared.u64 t, %1; cvt.u32.u64 %0, t; }" : "=r"(a) : "l"(p));
    return a;
}
__device__ __forceinline__ void split2(float v, uint16_t& hi, uint16_t& lo) {
    __nv_bfloat16 b0 = __float2bfloat16_rn(v);
    float r = v - __bfloat162float(b0);
    __nv_bfloat16 b1 = __float2bfloat16_rn(r);
    hi = __nv_bfloat16_raw(b0).x;
    lo = __nv_bfloat16_raw(b1).x;
}
__device__ __forceinline__ void cpa16(u32 dst, const void* src) {
    asm volatile("cp.async.cg.shared.global [%0], [%1], 16;" :: "r"(dst), "l"(src));
}
__device__ __forceinline__ void cpa_commit() { asm volatile("cp.async.commit_group;" ::: "memory"); }
__device__ __forceinline__ void cpwait1() { asm volatile("cp.async.wait_group 1;" ::: "memory"); }
__device__ __forceinline__ void cpwait0() { asm volatile("cp.async.wait_group 0;" ::: "memory"); }

__device__ __forceinline__ void ldsm_a(u32 addr, u32& r0, u32& r1, u32& r2, u32& r3) {
    asm volatile("ldmatrix.sync.aligned.m8n8.x4.shared.b16 {%0,%1,%2,%3}, [%4];"
                 : "=r"(r0), "=r"(r1), "=r"(r2), "=r"(r3) : "r"(addr));
}
__device__ __forceinline__ void ldsm_bt(u32 addr, u32& r0, u32& r1, u32& r2, u32& r3) {
    asm volatile("ldmatrix.sync.aligned.m8n8.x4.trans.shared.b16 {%0,%1,%2,%3}, [%4];"
                 : "=r"(r0), "=r"(r1), "=r"(r2), "=r"(r3) : "r"(addr));
}
__device__ __forceinline__ void mma16816(float* c, const u32* a, u32 b0, u32 b1) {
    asm volatile(
        "mma.sync.aligned.m16n8k16.row.col.f32.bf16.bf16.f32 "
        "{%0,%1,%2,%3}, {%4,%5,%6,%7}, {%8,%9}, {%0,%1,%2,%3};"
        : "+f"(c[0]), "+f"(c[1]), "+f"(c[2]), "+f"(c[3])
        : "r"(a[0]), "r"(a[1]), "r"(a[2]), "r"(a[3]), "r"(b0), "r"(b1));
}

// ---------------- setup ----------------

__global__ void k_conv(const float* __restrict__ W1, const float* __restrict__ W2) {
    int i = blockIdx.x * blockDim.x + threadIdx.x;
    uint16_t a, b;
    if (i < F_DIM * H_DIM) {
        split2(W1[i], a, b);
        ((uint16_t*)gW1a)[i] = a;
        ((uint16_t*)gW1b)[i] = b;
    } else if (i < 2 * F_DIM * H_DIM) {
        int j = i - F_DIM * H_DIM;
        split2(W2[j], a, b);
        ((uint16_t*)gW2a)[j] = a;
        ((uint16_t*)gW2b)[j] = b;
    }
}

__global__ void k_init(const float* __restrict__ x, float* __restrict__ out) {
    int i = blockIdx.x * blockDim.x + threadIdx.x;
    if (i >= BF) return;
    float v = x[i];
    out[i] = v;
    g_xc[i] = v;
    uint16_t a, b; split2(v, a, b);
    ((uint16_t*)gA0)[i] = a;
    ((uint16_t*)gA1)[i] = b;
}

// ---------------- GEMM1: h = tanh(xe @ W1x + te*wt + b1) ----------------
// grid (16,16): CTA 128x64, pass-fused chunks, 4 chunks of k64.
// smem per buf: A0 16K | A1 16K | B0 8K | B1 8K = 48K; x2 = 96K.

#define G1_BUF 49152u

__global__ __launch_bounds__(256, 2) void k_gemm1(const float* __restrict__ b1,
                                                  const float* __restrict__ wt,
                                                  float te) {
    extern __shared__ __align__(128) unsigned char smem[];
    const u32 sb = s2u(smem);
    const int tid = threadIdx.x, lane = tid & 31, wid = tid >> 5;
    const int wm = wid & 1, wn = wid >> 1;            // 2 x 4 warp grid, tile 64x16
    const int m0 = blockIdx.x * 128, n0 = blockIdx.y * 64;

    float acc[4][2][4];
    #pragma unroll
    for (int i = 0; i < 4; ++i)
        #pragma unroll
        for (int j = 0; j < 2; ++j)
            #pragma unroll
            for (int q = 0; q < 4; ++q) acc[i][j][q] = 0.0f;

    auto issue = [&](int c) {
        int ko = c * 64;
        u32 st = sb + (u32)(c & 1) * G1_BUF;
        #pragma unroll
        for (int t = 0; t < 4; ++t) {           // A planes, 128x64 each
            int cc = tid + t * 256;
            int r = cc >> 3, col = cc & 7;
            u32 off = (u32)r * 128 + (u32)((col ^ (r & 7)) << 4);
            size_t gsrc = (size_t)(m0 + r) * F_DIM + ko + col * 8;
            cpa16(st + off,          gA0 + gsrc);
            cpa16(st + 16384 + off,  gA1 + gsrc);
        }
        #pragma unroll
        for (int t = 0; t < 2; ++t) {           // B planes, 64x64 each
            int cc = tid + t * 256;
            int r = cc >> 3, col = cc & 7;
            u32 off = (u32)r * 128 + (u32)((col ^ (r & 7)) << 4);
            size_t gsrc = (size_t)(ko + r) * H_DIM + n0 + col * 8;
            cpa16(st + 32768 + off,  gW1a + gsrc);
            cpa16(st + 40960 + off,  gW1b + gsrc);
        }
        cpa_commit();
    };

    const int lr  = (lane & 7) + ((lane >> 3) & 1) * 8;
    const int hk  = lane >> 4;
    const int ar0 = wm * 64 + lr;
    const int asw = ar0 & 7;
    const int bsw = lr & 7;
    const int nblk = wn * 2 + hk;

    issue(0);
    #pragma unroll 1
    for (int c = 0; c < 4; ++c) {
        if (c + 1 < 4) { issue(c + 1); cpwait1(); } else { cpwait0(); }
        __syncthreads();
        u32 st = sb + (u32)(c & 1) * G1_BUF;
        #pragma unroll
        for (int ks = 0; ks < 4; ++ks) {
            u32 acol = (u32)((((ks << 1) + hk) ^ asw) << 4);
            u32 a0[4][4], a1[4][4];
            #pragma unroll
            for (int mi = 0; mi < 4; ++mi) {
                u32 rowoff = (u32)(ar0 + mi * 16) * 128 + acol;
                ldsm_a(st + rowoff,         a0[mi][0], a0[mi][1], a0[mi][2], a0[mi][3]);
                ldsm_a(st + 16384 + rowoff, a1[mi][0], a1[mi][1], a1[mi][2], a1[mi][3]);
            }
            u32 boff = (u32)(ks * 16 + lr) * 128 + (u32)((nblk ^ bsw) << 4);
            u32 b0[2][2], b1v[2][2];
            ldsm_bt(st + 32768 + boff, b0[0][0], b0[0][1], b0[1][0], b0[1][1]);
            ldsm_bt(st + 40960 + boff, b1v[0][0], b1v[0][1], b1v[1][0], b1v[1][1]);
            #pragma unroll
            for (int mi = 0; mi < 4; ++mi)
                #pragma unroll
                for (int nb = 0; nb < 2; ++nb) {
                    mma16816(acc[mi][nb], a0[mi], b0[nb][0], b0[nb][1]);
                    mma16816(acc[mi][nb], a1[mi], b0[nb][0], b0[nb][1]);
                    mma16816(acc[mi][nb], a0[mi], b1v[nb][0], b1v[nb][1]);
                }
        }
        __syncthreads();
    }

    // epilogue: bias + te*wt, tanh, split-2 -> H planes
    const int rbase = m0 + wm * 64 + (lane >> 2);
    const int cbase = n0 + wn * 16 + (lane & 3) * 2;
    #pragma unroll
    for (int nb = 0; nb < 2; ++nb) {
        int j = cbase + nb * 8;
        float2 bb = *(const float2*)(b1 + j);
        float2 ww = *(const float2*)(wt + j);
        float bias0 = bb.x + te * ww.x;
        float bias1 = bb.y + te * ww.y;
        #pragma unroll
        for (int mi = 0; mi < 4; ++mi) {
            #pragma unroll
            for (int h = 0; h < 2; ++h) {
                int row = rbase + mi * 16 + h * 8;
                float v0 = tanhf(acc[mi][nb][h * 2]     + bias0);
                float v1 = tanhf(acc[mi][nb][h * 2 + 1] + bias1);
                uint16_t h0, l0, h1, l1;
                split2(v0, h0, l0); split2(v1, h1, l1);
                size_t o = ((size_t)row * H_DIM + j) >> 1;
                ((u32*)gH0)[o] = (u32)h0 | ((u32)h1 << 16);
                ((u32*)gH1)[o] = (u32)l0 | ((u32)l1 << 16);
            }
        }
    }
}

// ---------------- GEMM2 + RK4: k = h @ W2 + b2 ----------------
// grid (32,4): CTA 64x64, K=1024 in 16 pass-fused chunks of 64.
// smem per buf: A0 8K | A1 8K | B0 8K | B1 8K = 32K; x2 = 64K.

#define G2_BUF 32768u

__global__ __launch_bounds__(256, 2) void k_gemm2(const float* __restrict__ b2,
                                                  float* __restrict__ out,
                                                  int e, int s, float ae) {
    extern __shared__ __align__(128) unsigned char smem[];
    const u32 sb = s2u(smem);
    const int tid = threadIdx.x, lane = tid & 31, wid = tid >> 5;
    const int wm = wid & 1, wn = wid >> 1;            // 2 x 4 warp grid, tile 32x16
    const int m0 = blockIdx.x * 64, n0 = blockIdx.y * 64;

    float acc[2][2][4];
    #pragma unroll
    for (int i = 0; i < 2; ++i)
        #pragma unroll
        for (int j = 0; j < 2; ++j)
            #pragma unroll
            for (int q = 0; q < 4; ++q) acc[i][j][q] = 0.0f;

    auto issue = [&](int c) {
        int ko = c * 64;
        u32 st = sb + (u32)(c & 1) * G2_BUF;
        #pragma unroll
        for (int t = 0; t < 2; ++t) {           // A planes, 64x64 each
            int cc = tid + t * 256;
            int r = cc >> 3, col = cc & 7;
            u32 off = (u32)r * 128 + (u32)((col ^ (r & 7)) << 4);
            size_t gsrc = (size_t)(m0 + r) * H_DIM + ko + col * 8;
            cpa16(st + off,         gH0 + gsrc);
            cpa16(st + 8192 + off,  gH1 + gsrc);
        }
        #pragma unroll
        for (int t = 0; t < 2; ++t) {           // B planes, 64x64 each
            int cc = tid + t * 256;
            int r = cc >> 3, col = cc & 7;
            u32 off = (u32)r * 128 + (u32)((col ^ (r & 7)) << 4);
            size_t gsrc = (size_t)(ko + r) * F_DIM + n0 + col * 8;
            cpa16(st + 16384 + off, gW2a + gsrc);
            cpa16(st + 24576 + off, gW2b + gsrc);
        }
        cpa_commit();
    };

    const int lr  = (lane & 7) + ((lane >> 3) & 1) * 8;
    const int hk  = lane >> 4;
    const int ar0 = wm * 32 + lr;
    const int asw = ar0 & 7;
    const int bsw = lr & 7;
    const int nblk = wn * 2 + hk;

    issue(0);
    #pragma unroll 1
    for (int c = 0; c < 16; ++c) {
        if (c + 1 < 16) { issue(c + 1); cpwait1(); } else { cpwait0(); }
        __syncthreads();
        u32 st = sb + (u32)(c & 1) * G2_BUF;
        #pragma unroll
        for (int ks = 0; ks < 4; ++ks) {
            u32 acol = (u32)((((ks << 1) + hk) ^ asw) << 4);
            u32 a0[2][4], a1[2][4];
            #pragma unroll
            for (int mi = 0; mi < 2; ++mi) {
                u32 rowoff = (u32)(ar0 + mi * 16) * 128 + acol;
                ldsm_a(st + rowoff,        a0[mi][0], a0[mi][1], a0[mi][2], a0[mi][3]);
                ldsm_a(st + 8192 + rowoff, a1[mi][0], a1[mi][1], a1[mi][2], a1[mi][3]);
            }
            u32 boff = (u32)(ks * 16 + lr) * 128 + (u32)((nblk ^ bsw) << 4);
            u32 b0[2][2], b1v[2][2];
            ldsm_bt(st + 16384 + boff, b0[0][0], b0[0][1], b0[1][0], b0[1][1]);
            ldsm_bt(st + 24576 + boff, b1v[0][0], b1v[0][1], b1v[1][0], b1v[1][1]);
            #pragma unroll
            for (int mi = 0; mi < 2; ++mi)
                #pragma unroll
                for (int nb = 0; nb < 2; ++nb) {
                    mma16816(acc[mi][nb], a0[mi], b0[nb][0], b0[nb][1]);
                    mma16816(acc[mi][nb], a1[mi], b0[nb][0], b0[nb][1]);
                    mma16816(acc[mi][nb], a0[mi], b1v[nb][0], b1v[nb][1]);
                }
        }
        __syncthreads();
    }

    // epilogue: RK4 state machine (CTA uniquely owns its 64x64 tile)
    const float dt6 = (1.0f / 99.0f) / 6.0f;
    const float be = (e == 1 || e == 2) ? 2.0f : 1.0f;
    const int rbase = m0 + wm * 32 + (lane >> 2);
    const int cbase = n0 + wn * 16 + (lane & 3) * 2;
    #pragma unroll
    for (int nb = 0; nb < 2; ++nb) {
        int j = cbase + nb * 8;
        float2 bb = *(const float2*)(b2 + j);
        #pragma unroll
        for (int mi = 0; mi < 2; ++mi) {
            #pragma unroll
            for (int h = 0; h < 2; ++h) {
                int row = rbase + mi * 16 + h * 8;
                size_t go = (size_t)row * F_DIM + j;
                float kv0 = acc[mi][nb][h * 2]     + bb.x;
                float kv1 = acc[mi][nb][h * 2 + 1] + bb.y;
                float2 xcv = *(const float2*)&g_xc[go];
                float a0, a1;
                if (e == 0) { a0 = kv0; a1 = kv1; }
                else {
                    float2 av = *(const float2*)&g_acc[go];
                    a0 = av.x + be * kv0; a1 = av.y + be * kv1;
                }
                float x0, x1;
                if (e < 3) {
                    x0 = xcv.x + ae * kv0; x1 = xcv.y + ae * kv1;
                    *(float2*)&g_acc[go] = make_float2(a0, a1);
                } else {
                    x0 = xcv.x + dt6 * a0; x1 = xcv.y + dt6 * a1;
                    *(float2*)&g_xc[go] = make_float2(x0, x1);
                    *(float2*)&out[(size_t)(s + 1) * BF + go] = make_float2(x0, x1);
                }
                uint16_t h0, l0, h1, l1;
                split2(x0, h0, l0); split2(x1, h1, l1);
                ((u32*)gA0)[go >> 1] = (u32)h0 | ((u32)h1 << 16);
                ((u32*)gA1)[go >> 1] = (u32)l0 | ((u32)l1 << 16);
            }
        }
    }
}

// ---------------- host ----------------

extern "C" void kernel_launch(void* const* d_in, const int* in_sizes, int n_in,
                              void* d_out, int out_size) {
    (void)in_sizes; (void)n_in; (void)out_size;
    const float* x  = (const float*)d_in[0];
    const float* W1 = (const float*)d_in[1];
    const float* b1 = (const float*)d_in[2];
    const float* W2 = (const float*)d_in[3];
    const float* b2 = (const float*)d_in[4];
    float* out = (float*)d_out;

    cudaFuncSetAttribute(k_gemm1, cudaFuncAttributeMaxDynamicSharedMemorySize, 2 * G1_BUF);
    cudaFuncSetAttribute(k_gemm2, cudaFuncAttributeMaxDynamicSharedMemorySize, 2 * G2_BUF);

    k_conv<<<2048, 256>>>(W1, W2);
    k_init<<<2048, 256>>>(x, out);

    const float dt = 1.0f / 99.0f;
    const float* wt = W1 + (size_t)F_DIM * H_DIM;   // time row of W1
    for (int s = 0; s < 99; ++s) {
        float t0 = s * dt;
        const float te_arr[4] = {t0, t0 + 0.5f * dt, t0 + 0.5f * dt, t0 + dt};
        const float ae_arr[4] = {0.5f * dt, 0.5f * dt, dt, 0.0f};
        for (int e = 0; e < 4; ++e) {
            k_gemm1<<<dim3(16, 16), 256, 2 * G1_BUF>>>(b1, wt, te_arr[e]);
            k_gemm2<<<dim3(32, 4), 256, 2 * G2_BUF>>>(b2, out, e, s, ae_arr[e]);
        }
    }
}